// round 15
// baseline (speedup 1.0000x reference)
#include <cuda_runtime.h>
#include <cuda_bf16.h>

#define IMG_H 512
#define IMG_W 512
#define FXc 500.0f
#define FYc 500.0f
#define CXc 256.0f
#define CYc 256.0f
#define NG  256
#define NCHUNK 4

// K = 0.5*log2(e) folded as sqrt(K) into mu*s params.
#define SQRT_K 0.8493218002880191f
// valid gate: num' > 0.1*sqrt(K) * den_u * rn (rn folded per-pixel)
#define VALID_C 0.08493218002880191f
// per-tile contribution cull threshold (log2): alpha_max < 2^-30
#define CULL_LOG2 (-30.0f)

typedef unsigned long long u64;

// Compacted, padded, packed (duplicated-pair) sorted gaussian params (global; L1-broadcast).
// Per gaussian: 5 x ulonglong2:
//  e0 = { {ms0',ms0'}, {ms1',ms1'} }
//  e1 = { {ms2',ms2'}, {s0,s0} }
//  e2 = { {s1,s1},     {s2,s2} }
//  e3 = { {la,la},     {c0,c0} }   la = log2( sigmoid(op)*exp(-0.5*m2) )
//  e4 = { {c1,c1},     {c2,c2} }
__device__ ulonglong2 g_packed[(NG + 32) * 5];
// Cull-structs, 2 x float4 per gaussian: {ms0',ms1',ms2',la}, {s0,s1,s2,0}.
__device__ float4 g_cull[(NG + 32) * 2];
__device__ int d_N;   // compacted list length (multiple of 8); no-op sentinel at index d_N

// 1024 threads: gaussian g = tid&255 paired with quarter q = tid>>8.
__global__ __launch_bounds__(1024) void prep_kernel(const float* __restrict__ pos,
                                                    const float* __restrict__ ls,
                                                    const float* __restrict__ rop,
                                                    const float* __restrict__ col) {
    const int tid = threadIdx.x;
    const int g = tid & 255;
    const int q = tid >> 8;
    __shared__ float zs[NG];
    __shared__ int pr4[4 * NG];
    __shared__ int pc4[4 * NG];
    __shared__ int ranks_s[NG];
    __shared__ int visr_s[NG];
    __shared__ int ptq[4];
    __shared__ int total_s;

    if (q == 0) zs[g] = pos[g * 3 + 2];
    __syncthreads();

    // Partial stable rank over this thread's quarter of j.
    const float z = zs[g];
    const int j0 = q * 64;
    int r = 0;
#pragma unroll 16
    for (int j = j0; j < j0 + 64; j++) {
        const float zj = zs[j];
        r += (zj < z) || (zj == z && j < g);
    }
    pr4[q * NG + g] = r;
    __syncthreads();

    float ms0, ms1, ms2, s0, s1, s2, la, c0, c1, c2;
    int vis = 0;
    if (q == 0) {
        const int rank = pr4[g] + pr4[NG + g] + pr4[2 * NG + g] + pr4[3 * NG + g];
        ranks_s[g] = rank;

        const float mu0 = pos[g * 3 + 0];
        const float mu1 = pos[g * 3 + 1];
        const float mu2 = z;

        const float e0 = expf(ls[g * 3 + 0]);
        const float e1 = expf(ls[g * 3 + 1]);
        const float e2 = expf(ls[g * 3 + 2]);
        s0 = 1.0f / (e0 * e0);
        s1 = 1.0f / (e1 * e1);
        s2 = 1.0f / (e2 * e2);

        ms0 = mu0 * s0;
        ms1 = mu1 * s1;
        ms2 = mu2 * s2;
        const float m2 = mu0 * ms0 + mu1 * ms1 + mu2 * ms2;

        const float a0 = 1.0f / (1.0f + expf(-rop[g]));
        la = log2f(a0) - 0.72134752044448170367f * m2;
        c0 = 1.0f / (1.0f + expf(-col[g * 3 + 0]));
        c1 = 1.0f / (1.0f + expf(-col[g * 3 + 1]));
        c2 = 1.0f / (1.0f + expf(-col[g * 3 + 2]));

        // EXACT frustum cull (R5): if num_max <= VALID_C*s2*0.81, alpha==0 everywhere.
        const float R = 0.511f;
        const float num_max = ms2 + R * (fabsf(ms0) + fabsf(ms1));
        vis = (num_max > VALID_C * s2 * 0.81f) ? 1 : 0;
        visr_s[rank] = vis;
    }
    __syncthreads();

    {
        const int rank = ranks_s[g];
        int pc = 0, pt = 0;
#pragma unroll 16
        for (int j = j0; j < j0 + 64; j++) {
            const int v = visr_s[j];
            pc += (j < rank) ? v : 0;
            pt += v;
        }
        pc4[q * NG + g] = pc;
        if (g == 0) ptq[q] = pt;
    }
    __syncthreads();

    if (q == 0) {
        const int cidx = pc4[g] + pc4[NG + g] + pc4[2 * NG + g] + pc4[3 * NG + g];
        const int total = ptq[0] + ptq[1] + ptq[2] + ptq[3];
        if (g == 0) total_s = total;

        if (vis) {
            const float msk0 = ms0 * SQRT_K;
            const float msk1 = ms1 * SQRT_K;
            const float msk2 = ms2 * SQRT_K;
            float* gp = (float*)&g_packed[cidx * 5];
            gp[0]  = msk0; gp[1]  = msk0;
            gp[2]  = msk1; gp[3]  = msk1;
            gp[4]  = msk2; gp[5]  = msk2;
            gp[6]  = s0;   gp[7]  = s0;
            gp[8]  = s1;   gp[9]  = s1;
            gp[10] = s2;   gp[11] = s2;
            gp[12] = la;   gp[13] = la;
            gp[14] = c0;   gp[15] = c0;
            gp[16] = c1;   gp[17] = c1;
            gp[18] = c2;   gp[19] = c2;
            g_cull[cidx * 2 + 0] = make_float4(msk0, msk1, msk2, la);
            g_cull[cidx * 2 + 1] = make_float4(s0, s1, s2, 0.0f);
        }
    }
    __syncthreads();

    // Pad to multiple of 8 PLUS a sentinel no-op at index N.
    // No-op: ms'=0 -> num'=0 fails gate -> alpha=0; s=1 -> den>0.
    const int total = total_s;
    const int N = ((total + 7) & ~7);
    const int padn = N - total + 1;        // includes sentinel at index N
    if (tid < padn) {
        const int e = total + tid;
        float* gp = (float*)&g_packed[e * 5];
#pragma unroll
        for (int k = 0; k < 20; k++) gp[k] = 0.0f;
        gp[6] = gp[7] = gp[8] = gp[9] = gp[10] = gp[11] = 1.0f;
        gp[12] = gp[13] = -100.0f;
        g_cull[e * 2 + 0] = make_float4(0.0f, 0.0f, 0.0f, -100.0f);
        g_cull[e * 2 + 1] = make_float4(1.0f, 1.0f, 1.0f, 0.0f);
    }
    if (tid == 0) d_N = N;
}

__device__ __forceinline__ float fast_ex2(float x) {
    float r;
    asm("ex2.approx.ftz.f32 %0, %1;" : "=f"(r) : "f"(x));
    return r;
}
__device__ __forceinline__ float fast_rcp(float x) {
    float r;
    asm("rcp.approx.ftz.f32 %0, %1;" : "=f"(r) : "f"(x));
    return r;
}
__device__ __forceinline__ u64 fma2(u64 a, u64 b, u64 c) {
    u64 d; asm("fma.rn.f32x2 %0, %1, %2, %3;" : "=l"(d) : "l"(a), "l"(b), "l"(c)); return d;
}
__device__ __forceinline__ u64 mul2(u64 a, u64 b) {
    u64 d; asm("mul.rn.f32x2 %0, %1, %2;" : "=l"(d) : "l"(a), "l"(b)); return d;
}
__device__ __forceinline__ u64 pk(float lo, float hi) {
    u64 d; asm("mov.b64 %0, {%1, %2};" : "=l"(d) : "f"(lo), "f"(hi)); return d;
}
__device__ __forceinline__ void upk(float& lo, float& hi, u64 a) {
    asm("mov.b64 {%0, %1}, %2;" : "=f"(lo), "=f"(hi) : "l"(a));
}

// One block = one QUARTER image row (128 px), 128 threads = 4 warps.
// Params read straight from global via __ldg (L1-broadcast, warm after 1st block/SM);
// shared memory holds only the tile index list + merge states (~7 KB -> 8 blocks/SM).
__global__ __launch_bounds__(128, 8) void render_kernel(float* __restrict__ out) {
    __shared__ float4 st[3 * 128];
    __shared__ unsigned short tidx[NG + 40];
    __shared__ unsigned int ballots[4];
    __shared__ int bsum[2];
    const int t = threadIdx.x;
    const int N = d_N;                        // list length; no-op sentinel at index N
    const int y  = blockIdx.x >> 2;
    const int qr = blockIdx.x & 3;
    const int c    = t >> 5;                  // warp = chunk
    const int slot = t & 31;

    const int xb = 4 * slot;
    const int xg = qr * 128 + xb;
    const float ay = (y + 0.5f - CYc) * (1.0f / FYc);
    const float ax_lo = (qr * 128 + 0.5f - CXc) * (1.0f / FXc);
    const float ax_hi = (qr * 128 + 127.5f - CXc) * (1.0f / FXc);

    float axs[4], rns[4];
#pragma unroll
    for (int p = 0; p < 4; p++) {
        const float ax = (xg + p + 0.5f - CXc) * (1.0f / FXc);
        axs[p] = ax;
        rns[p] = rsqrtf(fmaf(ax, ax, fmaf(ay, ay, 1.0f)));
    }

    const u64 axA  = pk(axs[0], axs[1]), axB  = pk(axs[2], axs[3]);
    const u64 axxA = mul2(axA, axA),     axxB = mul2(axB, axB);
    const u64 ay2  = pk(ay, ay);
    const u64 ayy2 = mul2(ay2, ay2);
    const u64 nvcrA = pk(-VALID_C * rns[0], -VALID_C * rns[1]);
    const u64 nvcrB = pk(-VALID_C * rns[2], -VALID_C * rns[3]);
    const u64 NEG1 = pk(-1.0f, -1.0f);

    // ---- Per-tile cull + ordered compaction (2 rounds x 128 gaussians) ----
    const float ayy_s = ay * ay;
    const float axm2 = (ax_lo * ax_hi <= 0.0f) ? 0.0f
                       : fminf(ax_lo * ax_lo, ax_hi * ax_hi);
    int base = 0;
    for (int rnd = 0; rnd < 2; rnd++) {
        const int i = rnd * 128 + t;
        bool keep = false;
        if (i < N) {
            const float4 ca = __ldg(&g_cull[i * 2 + 0]);
            const float b    = fmaf(ca.y, ay, ca.z);            // ms1'*ay + ms2'
            const float nmax = fmaxf(fmaf(ca.x, ax_lo, b),
                                     fmaf(ca.x, ax_hi, b));
            if (nmax > 0.0f) {
                const float4 cs = __ldg(&g_cull[i * 2 + 1]);
                const float dmin = fmaf(cs.x, axm2, fmaf(cs.y, ayy_s, cs.z));
                const float expo = nmax * nmax * fast_rcp(dmin);
                keep = (ca.w + expo > CULL_LOG2);
            }
        }
        const unsigned int ball = __ballot_sync(0xffffffffu, keep);
        if (slot == 0) ballots[c] = ball;
        __syncthreads();
        int off = base + __popc(ball & ((1u << slot) - 1u));
#pragma unroll
        for (int w = 0; w < 4; w++) off += (w < c) ? __popc(ballots[w]) : 0;
        if (keep) tidx[off] = (unsigned short)i;
        if (t == 0)
            bsum[rnd] = __popc(ballots[0]) + __popc(ballots[1]) +
                        __popc(ballots[2]) + __popc(ballots[3]);
        __syncthreads();
        base += bsum[rnd];
        __syncthreads();
    }
    const int M = base;
    const int Lc = ((M + 31) >> 5) << 3;      // per-chunk length, multiple of 8
    for (int k = M + t; k < NCHUNK * Lc; k += 128) tidx[k] = (unsigned short)N;
    __syncthreads();

    // ---- Composite this warp's chunk of the tile list ----
    u64 TA = pk(1.0f, 1.0f), TB = TA;
    u64 crA = pk(0.0f, 0.0f), cgA = crA, cbA = crA;
    u64 crB = crA, cgB = crA, cbB = crA;

    const int ibase = c * Lc;
    for (int ib = 0; ib < Lc; ib += 8) {
        float tA0, tA1, tB0, tB1;
        upk(tA0, tA1, TA);
        upk(tB0, tB1, TB);
        const float tmax = fmaxf(fmaxf(tA0, tA1), fmaxf(tB0, tB1));
        if (__all_sync(0xffffffffu, tmax < 1e-7f)) break;

#pragma unroll
        for (int j = 0; j < 8; j++) {
            const int idx = tidx[ibase + ib + j];     // warp-broadcast LDS
            const ulonglong2 e0 = __ldg(&g_packed[idx * 5 + 0]);
            const ulonglong2 e1 = __ldg(&g_packed[idx * 5 + 1]);
            const ulonglong2 e2 = __ldg(&g_packed[idx * 5 + 2]);
            const ulonglong2 e3 = __ldg(&g_packed[idx * 5 + 3]);
            const ulonglong2 e4 = __ldg(&g_packed[idx * 5 + 4]);

            // Row-shared terms (unnormalized ray u=(ax,ay,1); num^2/den scale-invariant).
            const u64 tnum = fma2(e0.y, ay2, e1.x);   // ms1*ay + ms2'
            const u64 tden = fma2(e2.x, ayy2, e2.y);  // s1*ay^2 + s2

            const u64 numA = fma2(e0.x, axA, tnum);
            const u64 numB = fma2(e0.x, axB, tnum);
            const u64 denA = fma2(e1.y, axxA, tden);
            const u64 denB = fma2(e1.y, axxB, tden);
            const u64 nnA = mul2(numA, numA);
            const u64 nnB = mul2(numB, numB);
            const u64 ggA = fma2(denA, nvcrA, numA);  // >0 <=> tau > 0.1
            const u64 ggB = fma2(denB, nvcrB, numB);

            float gA0, gA1, gB0, gB1, dA0, dA1, dB0, dB1;
            float qA0, qA1, qB0, qB1, la, la_;
            upk(gA0, gA1, ggA); upk(gB0, gB1, ggB);
            upk(dA0, dA1, denA); upk(dB0, dB1, denB);
            upk(qA0, qA1, nnA);  upk(qB0, qB1, nnB);
            upk(la, la_, e3.x);

            // Batched reciprocal: one MUFU rcp per pixel pair.
            const float rA = fast_rcp(dA0 * dA1);
            const float rB = fast_rcp(dB0 * dB1);
            const float iA0 = rA * dA1, iA1 = rA * dA0;
            const float iB0 = rB * dB1, iB1 = rB * dB0;

            const float argA0 = (gA0 > 0.0f) ? fmaf(qA0, iA0, la) : -1e30f;
            const float argA1 = (gA1 > 0.0f) ? fmaf(qA1, iA1, la) : -1e30f;
            const float argB0 = (gB0 > 0.0f) ? fmaf(qB0, iB0, la) : -1e30f;
            const float argB1 = (gB1 > 0.0f) ? fmaf(qB1, iB1, la) : -1e30f;

            const u64 alA = pk(fast_ex2(argA0), fast_ex2(argA1));
            const u64 alB = pk(fast_ex2(argB0), fast_ex2(argB1));

            const u64 wA = mul2(TA, alA);
            const u64 wB = mul2(TB, alB);
            crA = fma2(wA, e3.y, crA);  crB = fma2(wB, e3.y, crB);
            cgA = fma2(wA, e4.x, cgA);  cgB = fma2(wB, e4.x, cgB);
            cbA = fma2(wA, e4.y, cbA);  cbB = fma2(wB, e4.y, cbB);
            TA  = fma2(wA, NEG1, TA);   TB  = fma2(wB, NEG1, TB);
        }
    }

    float r4[4], g4[4], b4[4], t4[4];
    upk(r4[0], r4[1], crA); upk(r4[2], r4[3], crB);
    upk(g4[0], g4[1], cgA); upk(g4[2], g4[3], cgB);
    upk(b4[0], b4[1], cbA); upk(b4[2], b4[3], cbB);
    upk(t4[0], t4[1], TA);  upk(t4[2], t4[3], TB);

    if (c != 0) {
#pragma unroll
        for (int p = 0; p < 4; p++)
            st[(c - 1) * 128 + xb + p] = make_float4(r4[p], g4[p], b4[p], t4[p]);
    }
    __syncthreads();

    if (c == 0) {
        // final = i0 + T0*(i1 + T1*(i2 + T2*(i3 + T3)))
        float fr[4], fg[4], fb[4];
#pragma unroll
        for (int p = 0; p < 4; p++) {
            const float4 a1 = st[0 * 128 + xb + p];
            const float4 a2 = st[1 * 128 + xb + p];
            const float4 a3 = st[2 * 128 + xb + p];
            float r = a3.x + a3.w, g = a3.y + a3.w, b = a3.z + a3.w;
            r = fmaf(a2.w, r, a2.x); g = fmaf(a2.w, g, a2.y); b = fmaf(a2.w, b, a2.z);
            r = fmaf(a1.w, r, a1.x); g = fmaf(a1.w, g, a1.y); b = fmaf(a1.w, b, a1.z);
            fr[p] = fmaf(t4[p], r, r4[p]);
            fg[p] = fmaf(t4[p], g, g4[p]);
            fb[p] = fmaf(t4[p], b, b4[p]);
        }
        float4* o = (float4*)(out + (size_t)y * (IMG_W * 3) + 3 * xg);
        o[0] = make_float4(fr[0], fg[0], fb[0], fr[1]);
        o[1] = make_float4(fg[1], fb[1], fr[2], fg[2]);
        o[2] = make_float4(fb[2], fr[3], fg[3], fb[3]);
    }
}

extern "C" void kernel_launch(void* const* d_in, const int* in_sizes, int n_in,
                              void* d_out, int out_size) {
    const float* pos = (const float*)d_in[0];
    const float* ls  = (const float*)d_in[1];
    const float* rop = (const float*)d_in[2];
    const float* col = (const float*)d_in[3];
    float* out = (float*)d_out;

    prep_kernel<<<1, 1024>>>(pos, ls, rop, col);
    render_kernel<<<IMG_H * 4, 128>>>(out);
}

// round 16
// speedup vs baseline: 1.0020x; 1.0020x over previous
#include <cuda_runtime.h>
#include <cuda_bf16.h>

#define IMG_H 512
#define IMG_W 512
#define FXc 500.0f
#define FYc 500.0f
#define CXc 256.0f
#define CYc 256.0f
#define NG  256
#define NCHUNK 8

// K = 0.5*log2(e) folded as sqrt(K) into mu*s params.
#define SQRT_K 0.8493218002880191f
// valid gate: num' > 0.1*sqrt(K) * den_u * rn (rn folded per-pixel)
#define VALID_C 0.08493218002880191f
// per-tile contribution cull threshold (log2): alpha_max < 2^-30
#define CULL_LOG2 (-30.0f)

typedef unsigned long long u64;

// Compacted, padded, packed (duplicated-pair) sorted gaussian params.
// Per gaussian: 5 x ulonglong2:
//  e0 = { {ms0',ms0'}, {ms1',ms1'} }
//  e1 = { {ms2',ms2'}, {s0,s0} }
//  e2 = { {s1,s1},     {s2,s2} }
//  e3 = { {la,la},     {c0,c0} }   la = log2( sigmoid(op)*exp(-0.5*m2) )
//  e4 = { {c1,c1},     {c2,c2} }
__device__ ulonglong2 g_packed[(NG + 32) * 5];
__device__ int d_N;   // compacted list length (multiple of 8); no-op sentinel at index d_N

// 1024 threads: gaussian g = tid&255 paired with quarter q = tid>>8.
__global__ __launch_bounds__(1024) void prep_kernel(const float* __restrict__ pos,
                                                    const float* __restrict__ ls,
                                                    const float* __restrict__ rop,
                                                    const float* __restrict__ col) {
    const int tid = threadIdx.x;
    const int g = tid & 255;
    const int q = tid >> 8;
    __shared__ float zs[NG];
    __shared__ int pr4[4 * NG];
    __shared__ int pc4[4 * NG];
    __shared__ int ranks_s[NG];
    __shared__ int visr_s[NG];
    __shared__ int ptq[4];
    __shared__ int total_s;

    if (q == 0) zs[g] = pos[g * 3 + 2];
    __syncthreads();

    // Partial stable rank over this thread's quarter of j.
    const float z = zs[g];
    const int j0 = q * 64;
    int r = 0;
#pragma unroll 16
    for (int j = j0; j < j0 + 64; j++) {
        const float zj = zs[j];
        r += (zj < z) || (zj == z && j < g);
    }
    pr4[q * NG + g] = r;
    __syncthreads();

    float ms0, ms1, ms2, s0, s1, s2, la, c0, c1, c2;
    int vis = 0;
    if (q == 0) {
        const int rank = pr4[g] + pr4[NG + g] + pr4[2 * NG + g] + pr4[3 * NG + g];
        ranks_s[g] = rank;

        const float mu0 = pos[g * 3 + 0];
        const float mu1 = pos[g * 3 + 1];
        const float mu2 = z;

        const float e0 = expf(ls[g * 3 + 0]);
        const float e1 = expf(ls[g * 3 + 1]);
        const float e2 = expf(ls[g * 3 + 2]);
        s0 = 1.0f / (e0 * e0);
        s1 = 1.0f / (e1 * e1);
        s2 = 1.0f / (e2 * e2);

        ms0 = mu0 * s0;
        ms1 = mu1 * s1;
        ms2 = mu2 * s2;
        const float m2 = mu0 * ms0 + mu1 * ms1 + mu2 * ms2;

        const float a0 = 1.0f / (1.0f + expf(-rop[g]));
        la = log2f(a0) - 0.72134752044448170367f * m2;
        c0 = 1.0f / (1.0f + expf(-col[g * 3 + 0]));
        c1 = 1.0f / (1.0f + expf(-col[g * 3 + 1]));
        c2 = 1.0f / (1.0f + expf(-col[g * 3 + 2]));

        // EXACT frustum cull (R5): if num_max <= VALID_C*s2*0.81, alpha==0 everywhere.
        const float R = 0.511f;
        const float num_max = ms2 + R * (fabsf(ms0) + fabsf(ms1));
        vis = (num_max > VALID_C * s2 * 0.81f) ? 1 : 0;
        visr_s[rank] = vis;
    }
    __syncthreads();

    {
        const int rank = ranks_s[g];
        int pc = 0, pt = 0;
#pragma unroll 16
        for (int j = j0; j < j0 + 64; j++) {
            const int v = visr_s[j];
            pc += (j < rank) ? v : 0;
            pt += v;
        }
        pc4[q * NG + g] = pc;
        if (g == 0) ptq[q] = pt;
    }
    __syncthreads();

    if (q == 0) {
        const int cidx = pc4[g] + pc4[NG + g] + pc4[2 * NG + g] + pc4[3 * NG + g];
        const int total = ptq[0] + ptq[1] + ptq[2] + ptq[3];
        if (g == 0) total_s = total;

        if (vis) {
            float* gp = (float*)&g_packed[cidx * 5];
            gp[0]  = ms0 * SQRT_K; gp[1]  = gp[0];
            gp[2]  = ms1 * SQRT_K; gp[3]  = gp[2];
            gp[4]  = ms2 * SQRT_K; gp[5]  = gp[4];
            gp[6]  = s0;           gp[7]  = s0;
            gp[8]  = s1;           gp[9]  = s1;
            gp[10] = s2;           gp[11] = s2;
            gp[12] = la;           gp[13] = la;
            gp[14] = c0;           gp[15] = c0;
            gp[16] = c1;           gp[17] = c1;
            gp[18] = c2;           gp[19] = c2;
        }
    }
    __syncthreads();

    // Pad to multiple of 8 PLUS a sentinel no-op at index N.
    // No-op: ms'=0 -> num'=0 fails gate -> alpha=0; s=1 -> den>0.
    const int total = total_s;
    const int N = ((total + 7) & ~7);
    const int padn = N - total + 1;        // includes sentinel at index N
    if (tid < padn) {
        float* gp = (float*)&g_packed[(total + tid) * 5];
#pragma unroll
        for (int k = 0; k < 20; k++) gp[k] = 0.0f;
        gp[6] = gp[7] = gp[8] = gp[9] = gp[10] = gp[11] = 1.0f;
        gp[12] = gp[13] = -100.0f;
    }
    if (tid == 0) d_N = N;
}

__device__ __forceinline__ float fast_ex2(float x) {
    float r;
    asm("ex2.approx.ftz.f32 %0, %1;" : "=f"(r) : "f"(x));
    return r;
}
__device__ __forceinline__ float fast_rcp(float x) {
    float r;
    asm("rcp.approx.ftz.f32 %0, %1;" : "=f"(r) : "f"(x));
    return r;
}
__device__ __forceinline__ u64 fma2(u64 a, u64 b, u64 c) {
    u64 d; asm("fma.rn.f32x2 %0, %1, %2, %3;" : "=l"(d) : "l"(a), "l"(b), "l"(c)); return d;
}
__device__ __forceinline__ u64 mul2(u64 a, u64 b) {
    u64 d; asm("mul.rn.f32x2 %0, %1, %2;" : "=l"(d) : "l"(a), "l"(b)); return d;
}
__device__ __forceinline__ u64 pk(float lo, float hi) {
    u64 d; asm("mov.b64 %0, {%1, %2};" : "=l"(d) : "f"(lo), "f"(hi)); return d;
}
__device__ __forceinline__ void upk(float& lo, float& hi, u64 a) {
    asm("mov.b64 {%0, %1}, %2;" : "=f"(lo), "=f"(hi) : "l"(a));
}

// One block = one QUARTER image row (128 px), 256 threads = 8 warps.
// Warp c composites z-chunk c of the tile list for all 128 px (32 slots x 4 px).
// Params staged in shared (LDS broadcast); 8-deep in-block smem merge.
__global__ __launch_bounds__(256, 4) void render_kernel(float* __restrict__ out) {
    __shared__ ulonglong2 sg[(NG + 16) * 5];
    __shared__ float4 st[(NCHUNK - 1) * 128];
    __shared__ unsigned short tidx[NG + 64];
    __shared__ unsigned int ballots[8];
    __shared__ int bsum;
    const int t = threadIdx.x;
    const int N = d_N;                        // list length; no-op sentinel at index N
    const int y  = blockIdx.x >> 2;
    const int qr = blockIdx.x & 3;
    const int c    = t >> 5;                  // warp = chunk (0..7)
    const int slot = t & 31;

    for (int k = t; k < (N + 1) * 5; k += 256) sg[k] = g_packed[k];

    const int xb = 4 * slot;
    const int xg = qr * 128 + xb;
    const float ay = (y + 0.5f - CYc) * (1.0f / FYc);
    const float ax_lo = (qr * 128 + 0.5f - CXc) * (1.0f / FXc);
    const float ax_hi = (qr * 128 + 127.5f - CXc) * (1.0f / FXc);

    float axs[4], rns[4];
#pragma unroll
    for (int p = 0; p < 4; p++) {
        const float ax = (xg + p + 0.5f - CXc) * (1.0f / FXc);
        axs[p] = ax;
        rns[p] = rsqrtf(fmaf(ax, ax, fmaf(ay, ay, 1.0f)));
    }

    const u64 axA  = pk(axs[0], axs[1]), axB  = pk(axs[2], axs[3]);
    const u64 axxA = mul2(axA, axA),     axxB = mul2(axB, axB);
    const u64 ay2  = pk(ay, ay);
    const u64 ayy2 = mul2(ay2, ay2);
    const u64 nvcrA = pk(-VALID_C * rns[0], -VALID_C * rns[1]);
    const u64 nvcrB = pk(-VALID_C * rns[2], -VALID_C * rns[3]);
    const u64 NEG1 = pk(-1.0f, -1.0f);

    __syncthreads();

    // ---- Per-tile cull + ordered compaction (single round, thread t = gaussian t) ----
    {
        const float ayy_s = ay * ay;
        const float axm2 = (ax_lo * ax_hi <= 0.0f) ? 0.0f
                           : fminf(ax_lo * ax_lo, ax_hi * ax_hi);
        bool keep = false;
        if (t < N) {
            const float* gp = (const float*)&sg[t * 5];
            const float b    = fmaf(gp[2], ay, gp[4]);          // ms1'*ay + ms2'
            const float nmax = fmaxf(fmaf(gp[0], ax_lo, b),
                                     fmaf(gp[0], ax_hi, b));
            if (nmax > 0.0f) {
                const float dmin = fmaf(gp[6], axm2, fmaf(gp[8], ayy_s, gp[10]));
                const float expo = nmax * nmax * fast_rcp(dmin);
                keep = (gp[12] + expo > CULL_LOG2);
            }
        }
        const unsigned int ball = __ballot_sync(0xffffffffu, keep);
        if (slot == 0) ballots[c] = ball;
        __syncthreads();
        int off = __popc(ball & ((1u << slot) - 1u));
#pragma unroll
        for (int w = 0; w < 8; w++) off += (w < c) ? __popc(ballots[w]) : 0;
        if (keep) tidx[off] = (unsigned short)t;
        if (t == 0) {
            int s = 0;
#pragma unroll
            for (int w = 0; w < 8; w++) s += __popc(ballots[w]);
            bsum = s;
        }
        __syncthreads();
    }
    const int M = bsum;
    const int Lc = ((M + 63) >> 6) << 3;      // per-chunk length, multiple of 8; 8*Lc >= M
    for (int k = M + t; k < NCHUNK * Lc; k += 256) tidx[k] = (unsigned short)N;
    __syncthreads();

    // ---- Composite this warp's chunk of the tile list ----
    u64 TA = pk(1.0f, 1.0f), TB = TA;
    u64 crA = pk(0.0f, 0.0f), cgA = crA, cbA = crA;
    u64 crB = crA, cgB = crA, cbB = crA;

    const int ibase = c * Lc;
    for (int ib = 0; ib < Lc; ib += 8) {
        float tA0, tA1, tB0, tB1;
        upk(tA0, tA1, TA);
        upk(tB0, tB1, TB);
        const float tmax = fmaxf(fmaxf(tA0, tA1), fmaxf(tB0, tB1));
        if (__all_sync(0xffffffffu, tmax < 1e-7f)) break;

#pragma unroll
        for (int j = 0; j < 8; j++) {
            const int idx = tidx[ibase + ib + j];     // warp-broadcast LDS
            const ulonglong2 e0 = sg[idx * 5 + 0];
            const ulonglong2 e1 = sg[idx * 5 + 1];
            const ulonglong2 e2 = sg[idx * 5 + 2];
            const ulonglong2 e3 = sg[idx * 5 + 3];
            const ulonglong2 e4 = sg[idx * 5 + 4];

            // Row-shared terms (unnormalized ray u=(ax,ay,1); num^2/den scale-invariant).
            const u64 tnum = fma2(e0.y, ay2, e1.x);   // ms1*ay + ms2'
            const u64 tden = fma2(e2.x, ayy2, e2.y);  // s1*ay^2 + s2

            const u64 numA = fma2(e0.x, axA, tnum);
            const u64 numB = fma2(e0.x, axB, tnum);
            const u64 denA = fma2(e1.y, axxA, tden);
            const u64 denB = fma2(e1.y, axxB, tden);
            const u64 nnA = mul2(numA, numA);
            const u64 nnB = mul2(numB, numB);
            const u64 ggA = fma2(denA, nvcrA, numA);  // >0 <=> tau > 0.1
            const u64 ggB = fma2(denB, nvcrB, numB);

            float gA0, gA1, gB0, gB1, dA0, dA1, dB0, dB1;
            float qA0, qA1, qB0, qB1, la, la_;
            upk(gA0, gA1, ggA); upk(gB0, gB1, ggB);
            upk(dA0, dA1, denA); upk(dB0, dB1, denB);
            upk(qA0, qA1, nnA);  upk(qB0, qB1, nnB);
            upk(la, la_, e3.x);

            // Batched reciprocal: one MUFU rcp per pixel pair.
            const float rA = fast_rcp(dA0 * dA1);
            const float rB = fast_rcp(dB0 * dB1);
            const float iA0 = rA * dA1, iA1 = rA * dA0;
            const float iB0 = rB * dB1, iB1 = rB * dB0;

            const float argA0 = (gA0 > 0.0f) ? fmaf(qA0, iA0, la) : -1e30f;
            const float argA1 = (gA1 > 0.0f) ? fmaf(qA1, iA1, la) : -1e30f;
            const float argB0 = (gB0 > 0.0f) ? fmaf(qB0, iB0, la) : -1e30f;
            const float argB1 = (gB1 > 0.0f) ? fmaf(qB1, iB1, la) : -1e30f;

            const u64 alA = pk(fast_ex2(argA0), fast_ex2(argA1));
            const u64 alB = pk(fast_ex2(argB0), fast_ex2(argB1));

            const u64 wA = mul2(TA, alA);
            const u64 wB = mul2(TB, alB);
            crA = fma2(wA, e3.y, crA);  crB = fma2(wB, e3.y, crB);
            cgA = fma2(wA, e4.x, cgA);  cgB = fma2(wB, e4.x, cgB);
            cbA = fma2(wA, e4.y, cbA);  cbB = fma2(wB, e4.y, cbB);
            TA  = fma2(wA, NEG1, TA);   TB  = fma2(wB, NEG1, TB);
        }
    }

    float r4[4], g4[4], b4[4], t4[4];
    upk(r4[0], r4[1], crA); upk(r4[2], r4[3], crB);
    upk(g4[0], g4[1], cgA); upk(g4[2], g4[3], cgB);
    upk(b4[0], b4[1], cbA); upk(b4[2], b4[3], cbB);
    upk(t4[0], t4[1], TA);  upk(t4[2], t4[3], TB);

    if (c != 0) {
#pragma unroll
        for (int p = 0; p < 4; p++)
            st[(c - 1) * 128 + xb + p] = make_float4(r4[p], g4[p], b4[p], t4[p]);
    }
    __syncthreads();

    if (c == 0) {
        // final = i0 + T0*(i1 + T1*(i2 + ... (i7 + T7) ...))
        float fr[4], fg[4], fb[4];
#pragma unroll
        for (int p = 0; p < 4; p++) {
            float r = 0.0f, g = 0.0f, b = 0.0f, tcur = 1.0f;
            // fold from the back: start with chunk 7
            const float4 a7 = st[6 * 128 + xb + p];
            r = a7.x + a7.w; g = a7.y + a7.w; b = a7.z + a7.w;
#pragma unroll
            for (int k = 5; k >= 0; k--) {
                const float4 a = st[k * 128 + xb + p];
                r = fmaf(a.w, r, a.x);
                g = fmaf(a.w, g, a.y);
                b = fmaf(a.w, b, a.z);
            }
            (void)tcur;
            fr[p] = fmaf(t4[p], r, r4[p]);
            fg[p] = fmaf(t4[p], g, g4[p]);
            fb[p] = fmaf(t4[p], b, b4[p]);
        }
        float4* o = (float4*)(out + (size_t)y * (IMG_W * 3) + 3 * xg);
        o[0] = make_float4(fr[0], fg[0], fb[0], fr[1]);
        o[1] = make_float4(fg[1], fb[1], fr[2], fg[2]);
        o[2] = make_float4(fb[2], fr[3], fg[3], fb[3]);
    }
}

extern "C" void kernel_launch(void* const* d_in, const int* in_sizes, int n_in,
                              void* d_out, int out_size) {
    const float* pos = (const float*)d_in[0];
    const float* ls  = (const float*)d_in[1];
    const float* rop = (const float*)d_in[2];
    const float* col = (const float*)d_in[3];
    float* out = (float*)d_out;

    prep_kernel<<<1, 1024>>>(pos, ls, rop, col);
    render_kernel<<<IMG_H * 4, 256>>>(out);
}

// round 17
// speedup vs baseline: 1.0997x; 1.0975x over previous
#include <cuda_runtime.h>
#include <cuda_bf16.h>

#define IMG_H 512
#define IMG_W 512
#define FXc 500.0f
#define FYc 500.0f
#define CXc 256.0f
#define CYc 256.0f
#define NG  256
#define NCHUNK 4

// K = 0.5*log2(e) folded as sqrt(K) into mu*s params.
#define SQRT_K 0.8493218002880191f
// valid gate: num' > 0.1*sqrt(K) * den_u * rn (rn folded per-pixel)
#define VALID_C 0.08493218002880191f
// per-tile contribution cull threshold (log2): alpha_max < 2^-30
#define CULL_LOG2 (-30.0f)

typedef unsigned long long u64;

// Compacted, padded, packed (duplicated-pair) sorted gaussian params.
// Per gaussian: 5 x ulonglong2:
//  e0 = { {ms0',ms0'}, {ms1',ms1'} }
//  e1 = { {ms2',ms2'}, {s0,s0} }
//  e2 = { {s1,s1},     {s2,s2} }
//  e3 = { {la,la},     {c0,c0} }   la = log2( sigmoid(op)*exp(-0.5*m2) )
//  e4 = { {c1,c1},     {c2,c2} }
__device__ ulonglong2 g_packed[(NG + 32) * 5];
__device__ int d_N;   // compacted list length (multiple of 8); no-op sentinel at index d_N

// 1024 threads: gaussian g = tid&255 paired with quarter q = tid>>8.
__global__ __launch_bounds__(1024) void prep_kernel(const float* __restrict__ pos,
                                                    const float* __restrict__ ls,
                                                    const float* __restrict__ rop,
                                                    const float* __restrict__ col) {
    const int tid = threadIdx.x;
    const int g = tid & 255;
    const int q = tid >> 8;
    __shared__ float zs[NG];
    __shared__ int pr4[4 * NG];
    __shared__ int pc4[4 * NG];
    __shared__ int ranks_s[NG];
    __shared__ int visr_s[NG];
    __shared__ int ptq[4];
    __shared__ int total_s;

    if (q == 0) zs[g] = pos[g * 3 + 2];
    __syncthreads();

    // Partial stable rank over this thread's quarter of j.
    const float z = zs[g];
    const int j0 = q * 64;
    int r = 0;
#pragma unroll 16
    for (int j = j0; j < j0 + 64; j++) {
        const float zj = zs[j];
        r += (zj < z) || (zj == z && j < g);
    }
    pr4[q * NG + g] = r;
    __syncthreads();

    float ms0, ms1, ms2, s0, s1, s2, la, c0, c1, c2;
    int vis = 0;
    if (q == 0) {
        const int rank = pr4[g] + pr4[NG + g] + pr4[2 * NG + g] + pr4[3 * NG + g];
        ranks_s[g] = rank;

        const float mu0 = pos[g * 3 + 0];
        const float mu1 = pos[g * 3 + 1];
        const float mu2 = z;

        const float e0 = expf(ls[g * 3 + 0]);
        const float e1 = expf(ls[g * 3 + 1]);
        const float e2 = expf(ls[g * 3 + 2]);
        s0 = 1.0f / (e0 * e0);
        s1 = 1.0f / (e1 * e1);
        s2 = 1.0f / (e2 * e2);

        ms0 = mu0 * s0;
        ms1 = mu1 * s1;
        ms2 = mu2 * s2;
        const float m2 = mu0 * ms0 + mu1 * ms1 + mu2 * ms2;

        const float a0 = 1.0f / (1.0f + expf(-rop[g]));
        la = log2f(a0) - 0.72134752044448170367f * m2;
        c0 = 1.0f / (1.0f + expf(-col[g * 3 + 0]));
        c1 = 1.0f / (1.0f + expf(-col[g * 3 + 1]));
        c2 = 1.0f / (1.0f + expf(-col[g * 3 + 2]));

        // EXACT frustum cull (R5): if num_max <= VALID_C*s2*0.81, alpha==0 everywhere.
        const float R = 0.511f;
        const float num_max = ms2 + R * (fabsf(ms0) + fabsf(ms1));
        vis = (num_max > VALID_C * s2 * 0.81f) ? 1 : 0;
        visr_s[rank] = vis;
    }
    __syncthreads();

    {
        const int rank = ranks_s[g];
        int pc = 0, pt = 0;
#pragma unroll 16
        for (int j = j0; j < j0 + 64; j++) {
            const int v = visr_s[j];
            pc += (j < rank) ? v : 0;
            pt += v;
        }
        pc4[q * NG + g] = pc;
        if (g == 0) ptq[q] = pt;
    }
    __syncthreads();

    if (q == 0) {
        const int cidx = pc4[g] + pc4[NG + g] + pc4[2 * NG + g] + pc4[3 * NG + g];
        const int total = ptq[0] + ptq[1] + ptq[2] + ptq[3];
        if (g == 0) total_s = total;

        if (vis) {
            float* gp = (float*)&g_packed[cidx * 5];
            gp[0]  = ms0 * SQRT_K; gp[1]  = gp[0];
            gp[2]  = ms1 * SQRT_K; gp[3]  = gp[2];
            gp[4]  = ms2 * SQRT_K; gp[5]  = gp[4];
            gp[6]  = s0;           gp[7]  = s0;
            gp[8]  = s1;           gp[9]  = s1;
            gp[10] = s2;           gp[11] = s2;
            gp[12] = la;           gp[13] = la;
            gp[14] = c0;           gp[15] = c0;
            gp[16] = c1;           gp[17] = c1;
            gp[18] = c2;           gp[19] = c2;
        }
    }
    __syncthreads();

    // Pad to multiple of 8 PLUS a sentinel no-op at index N.
    // No-op: ms'=0 -> num'=0 fails gate -> alpha=0; s=1 -> den>0.
    const int total = total_s;
    const int N = ((total + 7) & ~7);
    const int padn = N - total + 1;        // includes sentinel at index N
    if (tid < padn) {
        float* gp = (float*)&g_packed[(total + tid) * 5];
#pragma unroll
        for (int k = 0; k < 20; k++) gp[k] = 0.0f;
        gp[6] = gp[7] = gp[8] = gp[9] = gp[10] = gp[11] = 1.0f;
        gp[12] = gp[13] = -100.0f;
    }
    if (tid == 0) d_N = N;

    // Allow the PDL-attributed render kernel to begin scheduling.
    cudaTriggerProgrammaticLaunchCompletion();
}

__device__ __forceinline__ float fast_ex2(float x) {
    float r;
    asm("ex2.approx.ftz.f32 %0, %1;" : "=f"(r) : "f"(x));
    return r;
}
__device__ __forceinline__ float fast_rcp(float x) {
    float r;
    asm("rcp.approx.ftz.f32 %0, %1;" : "=f"(r) : "f"(x));
    return r;
}
__device__ __forceinline__ u64 fma2(u64 a, u64 b, u64 c) {
    u64 d; asm("fma.rn.f32x2 %0, %1, %2, %3;" : "=l"(d) : "l"(a), "l"(b), "l"(c)); return d;
}
__device__ __forceinline__ u64 mul2(u64 a, u64 b) {
    u64 d; asm("mul.rn.f32x2 %0, %1, %2;" : "=l"(d) : "l"(a), "l"(b)); return d;
}
__device__ __forceinline__ u64 pk(float lo, float hi) {
    u64 d; asm("mov.b64 %0, {%1, %2};" : "=l"(d) : "f"(lo), "f"(hi)); return d;
}
__device__ __forceinline__ void upk(float& lo, float& hi, u64 a) {
    asm("mov.b64 {%0, %1}, %2;" : "=f"(lo), "=f"(hi) : "l"(a));
}

// One block = one QUARTER image row (128 px), 128 threads = 4 warps.
// PDL: ray setup runs while prep finishes; cudaGridDependencySynchronize() gates
// all reads of prep's outputs. Then: per-tile cull into z-ordered index list;
// warp c composites chunk c; in-block smem merge. (R14 architecture.)
__global__ __launch_bounds__(128, 8) void render_kernel(float* __restrict__ out) {
    __shared__ ulonglong2 sg[(NG + 16) * 5];
    __shared__ float4 st[3 * 128];
    __shared__ unsigned short tidx[NG + 40];
    __shared__ unsigned int ballots[4];
    __shared__ int bsum[2];
    const int t = threadIdx.x;
    const int y  = blockIdx.x >> 2;
    const int qr = blockIdx.x & 3;
    const int c    = t >> 5;                  // warp = chunk
    const int slot = t & 31;

    // ---- Ray setup first: independent of prep outputs (overlaps prep tail) ----
    const int xb = 4 * slot;
    const int xg = qr * 128 + xb;
    const float ay = (y + 0.5f - CYc) * (1.0f / FYc);
    const float ax_lo = (qr * 128 + 0.5f - CXc) * (1.0f / FXc);
    const float ax_hi = (qr * 128 + 127.5f - CXc) * (1.0f / FXc);

    float axs[4], rns[4];
#pragma unroll
    for (int p = 0; p < 4; p++) {
        const float ax = (xg + p + 0.5f - CXc) * (1.0f / FXc);
        axs[p] = ax;
        rns[p] = rsqrtf(fmaf(ax, ax, fmaf(ay, ay, 1.0f)));
    }

    const u64 axA  = pk(axs[0], axs[1]), axB  = pk(axs[2], axs[3]);
    const u64 axxA = mul2(axA, axA),     axxB = mul2(axB, axB);
    const u64 ay2  = pk(ay, ay);
    const u64 ayy2 = mul2(ay2, ay2);
    const u64 nvcrA = pk(-VALID_C * rns[0], -VALID_C * rns[1]);
    const u64 nvcrB = pk(-VALID_C * rns[2], -VALID_C * rns[3]);
    const u64 NEG1 = pk(-1.0f, -1.0f);

    // ---- Wait for prep's global writes to be visible ----
    cudaGridDependencySynchronize();

    const int N = d_N;                        // list length; no-op sentinel at index N
    for (int k = t; k < (N + 1) * 5; k += 128) sg[k] = g_packed[k];
    __syncthreads();

    // ---- Per-tile cull + ordered compaction (2 rounds x 128 gaussians) ----
    const float ayy_s = ay * ay;
    const float axm2 = (ax_lo * ax_hi <= 0.0f) ? 0.0f
                       : fminf(ax_lo * ax_lo, ax_hi * ax_hi);
    int base = 0;
    for (int rnd = 0; rnd < 2; rnd++) {
        const int i = rnd * 128 + t;
        bool keep = false;
        if (i < N) {
            const float* gp = (const float*)&sg[i * 5];
            const float b    = fmaf(gp[2], ay, gp[4]);          // ms1'*ay + ms2'
            const float nmax = fmaxf(fmaf(gp[0], ax_lo, b),
                                     fmaf(gp[0], ax_hi, b));
            if (nmax > 0.0f) {
                const float dmin = fmaf(gp[6], axm2, fmaf(gp[8], ayy_s, gp[10]));
                const float expo = nmax * nmax * fast_rcp(dmin);
                keep = (gp[12] + expo > CULL_LOG2);
            }
        }
        const unsigned int ball = __ballot_sync(0xffffffffu, keep);
        if (slot == 0) ballots[c] = ball;
        __syncthreads();
        int off = base + __popc(ball & ((1u << slot) - 1u));
#pragma unroll
        for (int w = 0; w < 4; w++) off += (w < c) ? __popc(ballots[w]) : 0;
        if (keep) tidx[off] = (unsigned short)i;
        if (t == 0)
            bsum[rnd] = __popc(ballots[0]) + __popc(ballots[1]) +
                        __popc(ballots[2]) + __popc(ballots[3]);
        __syncthreads();
        base += bsum[rnd];
        __syncthreads();
    }
    const int M = base;
    const int Lc = ((M + 31) >> 5) << 3;      // per-chunk length, multiple of 8
    for (int k = M + t; k < NCHUNK * Lc; k += 128) tidx[k] = (unsigned short)N;
    __syncthreads();

    // ---- Composite this warp's chunk of the tile list ----
    u64 TA = pk(1.0f, 1.0f), TB = TA;
    u64 crA = pk(0.0f, 0.0f), cgA = crA, cbA = crA;
    u64 crB = crA, cgB = crA, cbB = crA;

    const int ibase = c * Lc;
    for (int ib = 0; ib < Lc; ib += 8) {
        float tA0, tA1, tB0, tB1;
        upk(tA0, tA1, TA);
        upk(tB0, tB1, TB);
        const float tmax = fmaxf(fmaxf(tA0, tA1), fmaxf(tB0, tB1));
        if (__all_sync(0xffffffffu, tmax < 1e-7f)) break;

#pragma unroll
        for (int j = 0; j < 8; j++) {
            const int idx = tidx[ibase + ib + j];     // warp-broadcast LDS
            const ulonglong2 e0 = sg[idx * 5 + 0];
            const ulonglong2 e1 = sg[idx * 5 + 1];
            const ulonglong2 e2 = sg[idx * 5 + 2];
            const ulonglong2 e3 = sg[idx * 5 + 3];
            const ulonglong2 e4 = sg[idx * 5 + 4];

            // Row-shared terms (unnormalized ray u=(ax,ay,1); num^2/den scale-invariant).
            const u64 tnum = fma2(e0.y, ay2, e1.x);   // ms1*ay + ms2'
            const u64 tden = fma2(e2.x, ayy2, e2.y);  // s1*ay^2 + s2

            const u64 numA = fma2(e0.x, axA, tnum);
            const u64 numB = fma2(e0.x, axB, tnum);
            const u64 denA = fma2(e1.y, axxA, tden);
            const u64 denB = fma2(e1.y, axxB, tden);
            const u64 nnA = mul2(numA, numA);
            const u64 nnB = mul2(numB, numB);
            const u64 ggA = fma2(denA, nvcrA, numA);  // >0 <=> tau > 0.1
            const u64 ggB = fma2(denB, nvcrB, numB);

            float gA0, gA1, gB0, gB1, dA0, dA1, dB0, dB1;
            float qA0, qA1, qB0, qB1, la, la_;
            upk(gA0, gA1, ggA); upk(gB0, gB1, ggB);
            upk(dA0, dA1, denA); upk(dB0, dB1, denB);
            upk(qA0, qA1, nnA);  upk(qB0, qB1, nnB);
            upk(la, la_, e3.x);

            // Batched reciprocal: one MUFU rcp per pixel pair.
            const float rA = fast_rcp(dA0 * dA1);
            const float rB = fast_rcp(dB0 * dB1);
            const float iA0 = rA * dA1, iA1 = rA * dA0;
            const float iB0 = rB * dB1, iB1 = rB * dB0;

            const float argA0 = (gA0 > 0.0f) ? fmaf(qA0, iA0, la) : -1e30f;
            const float argA1 = (gA1 > 0.0f) ? fmaf(qA1, iA1, la) : -1e30f;
            const float argB0 = (gB0 > 0.0f) ? fmaf(qB0, iB0, la) : -1e30f;
            const float argB1 = (gB1 > 0.0f) ? fmaf(qB1, iB1, la) : -1e30f;

            const u64 alA = pk(fast_ex2(argA0), fast_ex2(argA1));
            const u64 alB = pk(fast_ex2(argB0), fast_ex2(argB1));

            const u64 wA = mul2(TA, alA);
            const u64 wB = mul2(TB, alB);
            crA = fma2(wA, e3.y, crA);  crB = fma2(wB, e3.y, crB);
            cgA = fma2(wA, e4.x, cgA);  cgB = fma2(wB, e4.x, cgB);
            cbA = fma2(wA, e4.y, cbA);  cbB = fma2(wB, e4.y, cbB);
            TA  = fma2(wA, NEG1, TA);   TB  = fma2(wB, NEG1, TB);
        }
    }

    float r4[4], g4[4], b4[4], t4[4];
    upk(r4[0], r4[1], crA); upk(r4[2], r4[3], crB);
    upk(g4[0], g4[1], cgA); upk(g4[2], g4[3], cgB);
    upk(b4[0], b4[1], cbA); upk(b4[2], b4[3], cbB);
    upk(t4[0], t4[1], TA);  upk(t4[2], t4[3], TB);

    if (c != 0) {
#pragma unroll
        for (int p = 0; p < 4; p++)
            st[(c - 1) * 128 + xb + p] = make_float4(r4[p], g4[p], b4[p], t4[p]);
    }
    __syncthreads();

    if (c == 0) {
        // final = i0 + T0*(i1 + T1*(i2 + T2*(i3 + T3)))
        float fr[4], fg[4], fb[4];
#pragma unroll
        for (int p = 0; p < 4; p++) {
            const float4 a1 = st[0 * 128 + xb + p];
            const float4 a2 = st[1 * 128 + xb + p];
            const float4 a3 = st[2 * 128 + xb + p];
            float r = a3.x + a3.w, g = a3.y + a3.w, b = a3.z + a3.w;
            r = fmaf(a2.w, r, a2.x); g = fmaf(a2.w, g, a2.y); b = fmaf(a2.w, b, a2.z);
            r = fmaf(a1.w, r, a1.x); g = fmaf(a1.w, g, a1.y); b = fmaf(a1.w, b, a1.z);
            fr[p] = fmaf(t4[p], r, r4[p]);
            fg[p] = fmaf(t4[p], g, g4[p]);
            fb[p] = fmaf(t4[p], b, b4[p]);
        }
        float4* o = (float4*)(out + (size_t)y * (IMG_W * 3) + 3 * xg);
        o[0] = make_float4(fr[0], fg[0], fb[0], fr[1]);
        o[1] = make_float4(fg[1], fb[1], fr[2], fg[2]);
        o[2] = make_float4(fb[2], fr[3], fg[3], fb[3]);
    }
}

extern "C" void kernel_launch(void* const* d_in, const int* in_sizes, int n_in,
                              void* d_out, int out_size) {
    const float* pos = (const float*)d_in[0];
    const float* ls  = (const float*)d_in[1];
    const float* rop = (const float*)d_in[2];
    const float* col = (const float*)d_in[3];
    float* out = (float*)d_out;

    prep_kernel<<<1, 1024>>>(pos, ls, rop, col);

    // Programmatic Dependent Launch: render may begin scheduling while prep
    // drains; cudaGridDependencySynchronize() inside render gates data reads.
    cudaLaunchConfig_t cfg = {};
    cfg.gridDim  = dim3(IMG_H * 4);
    cfg.blockDim = dim3(128);
    cfg.dynamicSmemBytes = 0;
    cfg.stream = 0;
    cudaLaunchAttribute attrs[1];
    attrs[0].id = cudaLaunchAttributeProgrammaticStreamSerialization;
    attrs[0].val.programmaticStreamSerializationAllowed = 1;
    cfg.attrs = attrs;
    cfg.numAttrs = 1;
    cudaLaunchKernelEx(&cfg, render_kernel, out);
}